// round 14
// baseline (speedup 1.0000x reference)
#include <cuda_runtime.h>
#include <math.h>
#include <stdint.h>

#define Bg   512
#define NPG  256
#define Rr   51

// ---------------- device scratch ----------------
__device__ float g_tables[5][Rr][128];
__device__ float g_PGpart[8][2][Bg][128];
__device__ float g_gsum[Bg][3][512];
__device__ float g_ght[Bg][3200];
__device__ float g_htacc[10][Bg][512];
__device__ uint4 g_Wt[3 * 16 * 512];       // [j][chunk][nb*32 + lane] b-frag quads
__device__ uint4 g_A[8192u * 32u * 32u];   // [G][s][lane] a-frag quads (128 MB)

__device__ __forceinline__ uint32_t packbf(float lo, float hi) {
    uint32_t p;
    asm("cvt.rn.bf16x2.f32 %0, %1, %2;" : "=r"(p) : "f"(hi), "f"(lo));
    return p;
}
__device__ __forceinline__ void mma_bf16(float* d, const uint32_t* a, uint32_t b0, uint32_t b1) {
    asm volatile(
        "mma.sync.aligned.m16n8k16.row.col.f32.bf16.bf16.f32 "
        "{%0,%1,%2,%3}, {%4,%5,%6,%7}, {%8,%9}, {%0,%1,%2,%3};"
        : "+f"(d[0]), "+f"(d[1]), "+f"(d[2]), "+f"(d[3])
        : "r"(a[0]), "r"(a[1]), "r"(a[2]), "r"(a[3]), "r"(b0), "r"(b1));
}
__device__ __forceinline__ uint32_t smem_u32(const void* p) {
    uint32_t a;
    asm("{ .reg .u64 t; cvta.to.shared.u64 t, %1; cvt.u32.u64 %0, t; }" : "=r"(a) : "l"(p));
    return a;
}
__device__ __forceinline__ void cp16(uint32_t dst, const void* src) {
    asm volatile("cp.async.ca.shared.global [%0], [%1], 16;" :: "r"(dst), "l"(src));
}
#define CP_COMMIT() asm volatile("cp.async.commit_group;" ::: "memory")
#define CP_WAIT2()  asm volatile("cp.async.wait_group 2;" ::: "memory")

// ---------------- kernel 1: setup (label tables + weight fragments) -----
__global__ void k_setup(const float* __restrict__ rel_emb,
                        const float* __restrict__ she,
                        const float* __restrict__ ste,
                        const float* __restrict__ A_w, const float* __restrict__ A_b,
                        const float* __restrict__ C_w, const float* __restrict__ C_b,
                        const float* __restrict__ E_w, const float* __restrict__ E_b)
{
    if (blockIdx.y < 5) {
        if (threadIdx.x >= 128) return;
        int r = blockIdx.x, t = blockIdx.y, d = threadIdx.x;
        const float* emb; const float* W; const float* bias = 0;
        switch (t) {
            case 0: emb = rel_emb; W = A_w + 512*128;  bias = A_b; break;
            case 1: emb = she;     W = C_w + 1536*128;             break;
            case 2: emb = she;     W = C_w + 1600*128; bias = C_b; break;
            case 3: emb = ste;     W = E_w + 1536*128;             break;
            default:emb = ste;     W = E_w + 1600*128; bias = E_b; break;
        }
        float acc = bias ? bias[d] : 0.f;
        for (int k = 0; k < 64; k++) acc += emb[r*64 + k] * W[k*128 + d];
        g_tables[t][r][d] = acc;
    } else {
        if (blockIdx.x >= 48) return;
        int c = blockIdx.x & 15;
        int j = blockIdx.x >> 4;
        const float* W = (j == 0) ? A_w : ((j == 1) ? C_w : E_w);
        uint4* dst = g_Wt + (size_t)(j*16 + c)*512;
        for (int r = 0; r < 2; r++) {
            int q = r*256 + threadIdx.x;
            int nb = q >> 5, idx = q & 31;
            int g = idx >> 2, t = idx & 3;
            int n = nb*8 + g;
            int k00 = c*32 + 2*t;
            uint4 v;
            v.x = packbf(W[(size_t)(k00 +  0)*128 + n], W[(size_t)(k00 +  1)*128 + n]);
            v.y = packbf(W[(size_t)(k00 +  8)*128 + n], W[(size_t)(k00 +  9)*128 + n]);
            v.z = packbf(W[(size_t)(k00 + 16)*128 + n], W[(size_t)(k00 + 17)*128 + n]);
            v.w = packbf(W[(size_t)(k00 + 24)*128 + n], W[(size_t)(k00 + 25)*128 + n]);
            dst[q] = v;
        }
    }
}

// ---------------- kernel 2: stage A as bf16 fragment quads --------------
__global__ void k_aprep(const float* __restrict__ flat)
{
    int G = blockIdx.x;
    #pragma unroll
    for (int r = 0; r < 4; r++) {
        int q = r*256 + threadIdx.x;
        int s = q >> 5, idx = q & 31;
        int g = idx >> 2, tt = idx & 3;
        size_t r0 = (size_t)G*16 + g, r1 = r0 + 8;
        int k0 = s*16 + 2*tt;
        float2 x  = *(const float2*)(flat + r0*512 + k0);
        float2 y  = *(const float2*)(flat + r1*512 + k0);
        float2 x8 = *(const float2*)(flat + r0*512 + k0 + 8);
        float2 y8 = *(const float2*)(flat + r1*512 + k0 + 8);
        uint4 v;
        v.x = packbf(x.x,  x.y);
        v.y = packbf(y.x,  y.y);
        v.z = packbf(x8.x, x8.y);
        v.w = packbf(y8.x, y8.y);
        g_A[((size_t)G*32 + s)*32 + idx] = v;
    }
}

// ---------------- kernel 3: per-graph PG terms, split-K -----------------
__global__ __launch_bounds__(256) void k_pg(
    const float* __restrict__ flat,
    const int* __restrict__ head_ids, const int* __restrict__ tail_ids,
    const float* __restrict__ C_w, const float* __restrict__ E_w)
{
    int m0    = blockIdx.x * 32;
    int kbase = blockIdx.y * 128;
    int path  = blockIdx.z;
    const float* W = (path == 0 ? C_w : E_w) + 512*128;
    __shared__ float As[32][33];
    __shared__ float Bs[32][132];
    __shared__ int rowA[32], rowB[32];
    int tid = threadIdx.x;
    if (tid < 32) {
        int g = m0 + tid;
        int h = head_ids[g], t = tail_ids[g];
        rowA[tid] = (path == 0) ? h : t;
        rowB[tid] = (path == 0) ? t : h;
    }
    __syncthreads();
    int tx = tid & 31, ty = tid >> 5;
    float acc[4][4] = {};
    for (int kc = 0; kc < 4; kc++) {
        int k0 = kbase + kc*32;
        for (int e = tid; e < 1024; e += 256) {
            int m = e >> 5, k = e & 31;
            int kg = k0 + k;
            int row = (kg < 512) ? rowA[m] : rowB[m];
            int kk  = (kg < 512) ? kg : kg - 512;
            As[m][k] = flat[(size_t)row*512 + kk];
        }
        for (int e = tid; e < 1024; e += 256) {
            int k = e >> 5, n = (e & 31) * 4;
            *(float4*)&Bs[k][n] = *(const float4*)&W[(size_t)(k0 + k)*128 + n];
        }
        __syncthreads();
        #pragma unroll
        for (int k = 0; k < 32; k++) {
            float4 b4 = *(const float4*)&Bs[k][tx*4];
            float a[4];
            #pragma unroll
            for (int i = 0; i < 4; i++) a[i] = As[ty*4 + i][k];
            #pragma unroll
            for (int i = 0; i < 4; i++) {
                acc[i][0] += a[i]*b4.x; acc[i][1] += a[i]*b4.y;
                acc[i][2] += a[i]*b4.z; acc[i][3] += a[i]*b4.w;
            }
        }
        __syncthreads();
    }
    #pragma unroll
    for (int i = 0; i < 4; i++)
        #pragma unroll
        for (int q = 0; q < 4; q++)
            g_PGpart[blockIdx.y][path][m0 + ty*4 + i][tx*4 + q] = acc[i][q];
}

// ---------------- kernel 4: fused pipeline (ring + fast segsum) ---------
// smem float offsets
#define AR_OFF   0        // 4 x 2048 floats (A ring)
#define BR_OFF   8192     // 4 x 2048 floats (B ring)
#define SW_OFF   16384    // 1536
#define SB_OFF   17920    // 16
#define PG_OFF   17936    // 256
#define WSM_OFF  18192    // 1536  ([node][12] gate layout)
#define NUM_OFF  19728    // 1536
#define DEN_OFF  21264    // 16
#define PRJ_OFF  21280    // 512
#define LBL_OFF  21792    // 384 ints
#define SM_FLOATS 22176

__global__ __launch_bounds__(256, 2) void k_fused_mma(
    const float* __restrict__ flat,
    const float* __restrict__ head_sister, const float* __restrict__ tail_sister,
    const int* __restrict__ t_label, const int* __restrict__ hst, const int* __restrict__ tst,
    const float* __restrict__ B_w, const float* __restrict__ B_b,
    const float* __restrict__ Dm_w, const float* __restrict__ Dm_b,
    const float* __restrict__ G_w, const float* __restrict__ G_b,
    const int* __restrict__ head_ids, const int* __restrict__ tail_ids,
    const int* __restrict__ rel_labels,
    const float* __restrict__ she, const float* __restrict__ ste)
{
    extern __shared__ float sm[];
    const uint4* ARing = (const uint4*)(sm + AR_OFF);
    const uint4* BRing = (const uint4*)(sm + BR_OFF);
    float* SW   = sm + SW_OFF;
    float* SB   = sm + SB_OFF;
    float* PG   = sm + PG_OFF;
    float* Wsm  = sm + WSM_OFF;   // [128][12]
    float* NUM  = sm + NUM_OFF;
    float* DEN  = sm + DEN_OFF;
    float* PRJ  = sm + PRJ_OFF;
    int*   lbl  = (int*)(sm + LBL_OFF);
    const uint32_t abase = smem_u32(sm + AR_OFF);
    const uint32_t bbase = smem_u32(sm + BR_OFF);

    const int b    = blockIdx.x;
    const int tid  = threadIdx.x;
    const int lane = tid & 31;
    const int wid  = tid >> 5;
    const int warpM = (wid & 3) * 32;
    const int warpN = (wid >> 2) * 64;
    const int qr = lane >> 2;
    const int qc = lane & 3;
    const int GlocBase = (wid & 3) * 2;
    const int nbBase   = (wid >> 2) * 8;

    for (int i = tid; i < 512; i += 256) {
        SW[i] = B_w[i]; SW[512 + i] = Dm_w[i]; SW[1024 + i] = G_w[i];
    }
    if (tid < 12) {
        int p = tid >> 2, l = tid & 3;
        SB[tid] = (p == 0) ? B_b[l] : ((p == 1) ? Dm_b[l] : G_b[l]);
        DEN[tid] = 0.f;
    }
    {
        int path = tid >> 7, col = tid & 127;
        float s = 0.f;
        #pragma unroll
        for (int q = 0; q < 8; q++) s += g_PGpart[q][path][b][col];
        PG[tid] = s;
    }
    for (int i = tid; i < 1536; i += 256) NUM[i] = 0.f;
    __syncthreads();

    // per-thread copy indices (constant across chunks)
    const int cGl0 = tid >> 6,        cRem0 = tid & 63;
    const int cSl0 = cRem0 >> 5,      cIdx0 = cRem0 & 31;
    const int cGl1 = (256 + tid) >> 6, cRem1 = (256 + tid) & 63;
    const int cSl1 = cRem1 >> 5,      cIdx1 = cRem1 & 31;

    for (int mt = 0; mt < 2; mt++) {
        const int rowbase = b*NPG + mt*128;
        const int Gbase = rowbase >> 4;
        if (tid < 128) {
            lbl[tid]       = t_label[rowbase + tid];
            lbl[128 + tid] = hst[rowbase + tid];
            lbl[256 + tid] = tst[rowbase + tid];
        }
        __syncthreads();

        for (int j = 0; j < 3; j++) {
            float acc[2][8][4];
            #pragma unroll
            for (int mi = 0; mi < 2; mi++)
                #pragma unroll
                for (int ni = 0; ni < 8; ni++)
                    #pragma unroll
                    for (int q = 0; q < 4; q++) acc[mi][ni][q] = 0.f;

            const uint4* WjBlk = g_Wt + (size_t)j*16*512;

            // prologue: issue chunks 0 and 1
            #pragma unroll
            for (int pc = 0; pc < 2; pc++) {
                uint32_t ad = abase + pc*8192 + tid*16;
                uint32_t bd = bbase + pc*8192 + tid*16;
                cp16(ad,        g_A + ((size_t)(Gbase + cGl0)*32 + 2*pc + cSl0)*32 + cIdx0);
                cp16(ad + 4096, g_A + ((size_t)(Gbase + cGl1)*32 + 2*pc + cSl1)*32 + cIdx1);
                cp16(bd,        WjBlk + (size_t)pc*512 + tid);
                cp16(bd + 4096, WjBlk + (size_t)pc*512 + 256 + tid);
                CP_COMMIT();
            }

            for (int c = 0; c < 16; c++) {
                if (c + 2 < 16) {
                    int nc = c + 2, buf = nc & 3;
                    uint32_t ad = abase + buf*8192 + tid*16;
                    uint32_t bd = bbase + buf*8192 + tid*16;
                    cp16(ad,        g_A + ((size_t)(Gbase + cGl0)*32 + 2*nc + cSl0)*32 + cIdx0);
                    cp16(ad + 4096, g_A + ((size_t)(Gbase + cGl1)*32 + 2*nc + cSl1)*32 + cIdx1);
                    cp16(bd,        WjBlk + (size_t)nc*512 + tid);
                    cp16(bd + 4096, WjBlk + (size_t)nc*512 + 256 + tid);
                }
                CP_COMMIT();
                CP_WAIT2();
                __syncthreads();

                const uint4* Ab = ARing + (c & 3)*512;
                const uint4* Bb = BRing + (c & 3)*512;
                uint4 a00 = Ab[ GlocBase      *64      + lane];
                uint4 a01 = Ab[ GlocBase      *64 + 32 + lane];
                uint4 a10 = Ab[(GlocBase + 1) *64      + lane];
                uint4 a11 = Ab[(GlocBase + 1) *64 + 32 + lane];
                #pragma unroll
                for (int ni = 0; ni < 8; ni++) {
                    uint4 bv = Bb[(nbBase + ni)*32 + lane];
                    mma_bf16(acc[0][ni], (const uint32_t*)&a00, bv.x, bv.y);
                    mma_bf16(acc[0][ni], (const uint32_t*)&a01, bv.z, bv.w);
                    mma_bf16(acc[1][ni], (const uint32_t*)&a10, bv.x, bv.y);
                    mma_bf16(acc[1][ni], (const uint32_t*)&a11, bv.z, bv.w);
                }
            }
            __syncthreads();
            {
                float bvv = SB[j*4 + (tid & 3)];
                PRJ[tid]       = bvv;
                PRJ[tid + 256] = bvv;
            }
            __syncthreads();

            #pragma unroll
            for (int mi = 0; mi < 2; mi++) {
                #pragma unroll
                for (int h = 0; h < 2; h++) {
                    int r = warpM + mi*16 + qr + h*8;
                    int lT = lbl[r], lH = lbl[128 + r], lS = lbl[256 + r];
                    float p0 = 0.f, p1 = 0.f, p2 = 0.f, p3 = 0.f;
                    #pragma unroll
                    for (int ni = 0; ni < 8; ni++) {
                        int col = warpN + ni*8 + qc*2;
                        float v0 = acc[mi][ni][h*2], v1 = acc[mi][ni][h*2 + 1];
                        float add0, add1;
                        if (j == 0) {
                            float2 t = *(const float2*)&g_tables[0][lT][col];
                            add0 = t.x; add1 = t.y;
                        } else if (j == 1) {
                            float2 t1 = *(const float2*)&g_tables[1][lH][col];
                            float2 t2 = *(const float2*)&g_tables[2][lT][col];
                            add0 = PG[col] + t1.x + t2.x;
                            add1 = PG[col + 1] + t1.y + t2.y;
                        } else {
                            float2 t1 = *(const float2*)&g_tables[3][lS][col];
                            float2 t2 = *(const float2*)&g_tables[4][lT][col];
                            add0 = PG[128 + col] + t1.x + t2.x;
                            add1 = PG[128 + col + 1] + t1.y + t2.y;
                        }
                        float H0 = fmaxf(v0 + add0, 0.f);
                        float H1 = fmaxf(v1 + add1, 0.f);
                        const float* w = SW + j*512 + col*4;
                        p0 += H0*w[0] + H1*w[4];
                        p1 += H0*w[1] + H1*w[5];
                        p2 += H0*w[2] + H1*w[6];
                        p3 += H0*w[3] + H1*w[7];
                    }
                    p0 += __shfl_xor_sync(0xffffffffu, p0, 1);
                    p0 += __shfl_xor_sync(0xffffffffu, p0, 2);
                    p1 += __shfl_xor_sync(0xffffffffu, p1, 1);
                    p1 += __shfl_xor_sync(0xffffffffu, p1, 2);
                    p2 += __shfl_xor_sync(0xffffffffu, p2, 1);
                    p2 += __shfl_xor_sync(0xffffffffu, p2, 2);
                    p3 += __shfl_xor_sync(0xffffffffu, p3, 1);
                    p3 += __shfl_xor_sync(0xffffffffu, p3, 2);
                    float pl = (qc == 0) ? p0 : ((qc == 1) ? p1 : ((qc == 2) ? p2 : p3));
                    atomicAdd(&PRJ[r*4 + qc], pl);
                }
            }
            __syncthreads();
            if (tid < 128) {
                int m = tid;
                float g0 = 1.f/(1.f + expf(-PRJ[m*4 + 0]));
                float g1 = 1.f/(1.f + expf(-PRJ[m*4 + 1]));
                float g2 = 1.f/(1.f + expf(-PRJ[m*4 + 2]));
                float g3 = 1.f/(1.f + expf(-PRJ[m*4 + 3]));
                if (j == 1) {
                    const float* hsv = head_sister + (size_t)(rowbase + m)*4;
                    g0 *= hsv[0]; g1 *= hsv[1]; g2 *= hsv[2]; g3 *= hsv[3];
                } else if (j == 2) {
                    const float* tsv = tail_sister + (size_t)(rowbase + m)*4;
                    g0 *= tsv[0]; g1 *= tsv[1]; g2 *= tsv[2]; g3 *= tsv[3];
                }
                *(float4*)(Wsm + m*12 + j*4) = make_float4(g0, g1, g2, g3);
            }
            __syncthreads();
        }

        // weighted segment sums for this tile ([node][12] gates, broadcast)
        {
            const int cp = tid*2;
            const int l  = tid >> 6;
            float s00=0,s01=0,s10=0,s11=0,s20=0,s21=0;
            const float* fb = flat + (size_t)rowbase*512 + cp;
            #pragma unroll 2
            for (int n = 0; n < 128; n++) {
                float2 v = *(const float2*)(fb + (size_t)n*512);
                float w0 = Wsm[n*12 + l];
                float w1 = Wsm[n*12 + 4 + l];
                float w2 = Wsm[n*12 + 8 + l];
                s00 += w0*v.x; s01 += w0*v.y;
                s10 += w1*v.x; s11 += w1*v.y;
                s20 += w2*v.x; s21 += w2*v.y;
            }
            NUM[0*512 + cp] += s00; NUM[0*512 + cp + 1] += s01;
            NUM[1*512 + cp] += s10; NUM[1*512 + cp + 1] += s11;
            NUM[2*512 + cp] += s20; NUM[2*512 + cp + 1] += s21;
            if (tid < 12) {
                float s = 0.f;
                for (int n = 0; n < 128; n++) s += Wsm[n*12 + tid];
                DEN[tid] += s;
            }
        }
        __syncthreads();
    }

    // finalize means + build g_ht rows (folded k_ght)
    {
        int h = head_ids[b], t = tail_ids[b];
        const int cp = tid*2;
        const int l  = tid >> 6;
        float2 n0 = *(const float2*)&NUM[0*512 + cp];
        float2 n1 = *(const float2*)&NUM[1*512 + cp];
        float2 n2 = *(const float2*)&NUM[2*512 + cp];
        float d0 = DEN[0*4 + l], d1 = DEN[1*4 + l], d2 = DEN[2*4 + l];
        float2 gs0 = make_float2(n0.x/d0, n0.y/d0);
        float2 ghs = make_float2(n1.x/d1, n1.y/d1);
        float2 gts = make_float2(n2.x/d2, n2.y/d2);
        *(float2*)&g_gsum[b][0][cp] = gs0;
        *(float2*)&g_gsum[b][1][cp] = ghs;
        *(float2*)&g_gsum[b][2][cp] = gts;
        float2 hv = *(const float2*)(flat + (size_t)h*512 + cp);
        float2 tv = *(const float2*)(flat + (size_t)t*512 + cp);
        float* out = g_ght[b];
        *(float2*)&out[cp]          = make_float2(ghs.x*hv.x, ghs.y*hv.y);
        *(float2*)&out[512 + cp]    = make_float2(gts.x*tv.x, gts.y*tv.y);
        *(float2*)&out[1024 + cp]   = ghs;
        *(float2*)&out[1536 + cp]   = gts;
        *(float2*)&out[2048 + cp]   = hv;
        *(float2*)&out[2560 + cp]   = tv;
        if (tid < 64) {
            int r = rel_labels[b];
            out[3072 + tid] = she[r*64 + tid];
            out[3136 + tid] = ste[r*64 + tid];
        }
    }
}

// ---------------- kernel 5: ht GEMM split-K 10 (partials) ---------------
__global__ __launch_bounds__(256) void k_ht(const float* __restrict__ ht_w)
{
    __shared__ float As2[64][33], Bs2[32][65];
    int m0 = blockIdx.y*64, n0 = blockIdx.x*64, kbase = blockIdx.z*320;
    int tid = threadIdx.x, tx = tid & 15, ty = tid >> 4;
    float acc[4][4] = {};
    for (int kc = 0; kc < 10; kc++) {
        int k0 = kbase + kc*32;
        #pragma unroll
        for (int r = 0; r < 8; r++) {
            int e = r*256 + tid; int m = e >> 5, k = e & 31;
            As2[m][k] = g_ght[m0 + m][k0 + k];
        }
        #pragma unroll
        for (int r = 0; r < 8; r++) {
            int e = r*256 + tid; int k = e >> 6, n = e & 63;
            Bs2[k][n] = ht_w[(size_t)(k0 + k)*512 + n0 + n];
        }
        __syncthreads();
        #pragma unroll
        for (int k = 0; k < 32; k++) {
            float a[4], bv[4];
            #pragma unroll
            for (int i = 0; i < 4; i++) { a[i] = As2[ty*4 + i][k]; bv[i] = Bs2[k][tx*4 + i]; }
            #pragma unroll
            for (int i = 0; i < 4; i++)
                #pragma unroll
                for (int q = 0; q < 4; q++) acc[i][q] += a[i]*bv[q];
        }
        __syncthreads();
    }
    #pragma unroll
    for (int i = 0; i < 4; i++)
        #pragma unroll
        for (int q = 0; q < 4; q++)
            g_htacc[blockIdx.z][m0 + ty*4 + i][n0 + tx*4 + q] = acc[i][q];
}

// ---------------- kernel 6: fc + out -------------------------------------
__global__ void k_final(const float* __restrict__ flat,
                        const int* __restrict__ head_ids, const int* __restrict__ tail_ids,
                        const int* __restrict__ rel_labels, const float* __restrict__ rel_emb,
                        const float* __restrict__ ht_b,
                        const float* __restrict__ fc_w, const float* __restrict__ fc_b,
                        const float* __restrict__ out_w, const float* __restrict__ out_b,
                        float* __restrict__ out)
{
    __shared__ float rep[2112];
    __shared__ float red[256][17];
    int b = blockIdx.x, tid = threadIdx.x;
    int h = head_ids[b], t = tail_ids[b];
    {
        int c = tid*2;
        *(float2*)&rep[c]        = *(const float2*)&g_gsum[b][0][c];
        *(float2*)&rep[512 + c]  = *(const float2*)(flat + (size_t)h*512 + c);
        *(float2*)&rep[1024 + c] = *(const float2*)(flat + (size_t)t*512 + c);
        float2 s = make_float2(0.f, 0.f);
        #pragma unroll
        for (int q = 0; q < 10; q++) {
            float2 p = *(const float2*)&g_htacc[q][b][c];
            s.x += p.x; s.y += p.y;
        }
        float2 hb2 = *(const float2*)&ht_b[c];
        rep[1536 + c]     = fmaxf(s.x + hb2.x, 0.f);
        rep[1536 + c + 1] = fmaxf(s.y + hb2.y, 0.f);
    }
    if (tid < 64) rep[2048 + tid] = rel_emb[rel_labels[b]*64 + tid];
    __syncthreads();

    float acc[16];
    #pragma unroll
    for (int j = 0; j < 16; j++) acc[j] = 0.f;
    for (int k = tid; k < 2112; k += 256) {
        float x = rep[k];
        const float4* w = (const float4*)(fc_w + (size_t)k*16);
        #pragma unroll
        for (int v = 0; v < 4; v++) {
            float4 ww = w[v];
            acc[v*4+0] += x*ww.x; acc[v*4+1] += x*ww.y;
            acc[v*4+2] += x*ww.z; acc[v*4+3] += x*ww.w;
        }
    }
    #pragma unroll
    for (int j = 0; j < 16; j++) red[tid][j] = acc[j];
    __syncthreads();
    for (int s = 128; s >= 1; s >>= 1) {
        if (tid < s) {
            #pragma unroll
            for (int j = 0; j < 16; j++) red[tid][j] += red[tid + s][j];
        }
        __syncthreads();
    }
    if (tid == 0) {
        float o = out_b[0];
        #pragma unroll
        for (int j = 0; j < 16; j++) o += fmaxf(red[0][j] + fc_b[j], 0.f) * out_w[j];
        out[b] = o;
    }
}

// ---------------- launch ------------------------------------------------
extern "C" void kernel_launch(void* const* d_in, const int* in_sizes, int n_in,
                              void* d_out, int out_size)
{
    const float* node_repr = (const float*)d_in[0];
    const float* head_sis  = (const float*)d_in[1];
    const float* tail_sis  = (const float*)d_in[2];
    const int*   t_label   = (const int*)d_in[3];
    const int*   hstp      = (const int*)d_in[4];
    const int*   tstp      = (const int*)d_in[5];
    const int*   head_ids  = (const int*)d_in[7];
    const int*   tail_ids  = (const int*)d_in[8];
    const int*   rel_lab   = (const int*)d_in[9];
    const float* rel_emb   = (const float*)d_in[10];
    const float* she       = (const float*)d_in[11];
    const float* ste       = (const float*)d_in[12];
    const float* A_w  = (const float*)d_in[13]; const float* A_b  = (const float*)d_in[14];
    const float* B_w  = (const float*)d_in[15]; const float* B_b  = (const float*)d_in[16];
    const float* C_w  = (const float*)d_in[17]; const float* C_b  = (const float*)d_in[18];
    const float* Dm_w = (const float*)d_in[19]; const float* Dm_b = (const float*)d_in[20];
    const float* E_w  = (const float*)d_in[21]; const float* E_b  = (const float*)d_in[22];
    const float* G_w  = (const float*)d_in[23]; const float* G_b  = (const float*)d_in[24];
    const float* ht_w = (const float*)d_in[25]; const float* ht_b = (const float*)d_in[26];
    const float* fc_w = (const float*)d_in[27]; const float* fc_b = (const float*)d_in[28];
    const float* out_w= (const float*)d_in[29]; const float* out_b= (const float*)d_in[30];
    float* out = (float*)d_out;

    const int smemBytes = SM_FLOATS * 4;
    cudaFuncSetAttribute(k_fused_mma, cudaFuncAttributeMaxDynamicSharedMemorySize, smemBytes);

    k_setup<<<dim3(Rr, 6), 256>>>(rel_emb, she, ste, A_w, A_b, C_w, C_b, E_w, E_b);
    k_aprep<<<8192, 256>>>(node_repr);
    k_pg<<<dim3(16, 8, 2), 256>>>(node_repr, head_ids, tail_ids, C_w, E_w);
    k_fused_mma<<<Bg, 256, smemBytes>>>(node_repr, head_sis, tail_sis, t_label, hstp, tstp,
                                        B_w, B_b, Dm_w, Dm_b, G_w, G_b,
                                        head_ids, tail_ids, rel_lab, she, ste);
    k_ht<<<dim3(8, 8, 10), 256>>>(ht_w);
    k_final<<<Bg, 256>>>(node_repr, head_ids, tail_ids, rel_lab, rel_emb, ht_b,
                         fc_w, fc_b, out_w, out_b, out);
}

// round 16
// speedup vs baseline: 1.0697x; 1.0697x over previous
#include <cuda_runtime.h>
#include <cuda_bf16.h>
#include <math.h>
#include <stdint.h>

#define Bg   512
#define NPG  256
#define Rr   51

// ---------------- device scratch ----------------
__device__ float g_tables[5][Rr][128];
__device__ float g_PGpart[8][2][Bg][128];
__device__ float g_gsum[Bg][3][512];
__device__ float g_ght[Bg][3200];
__device__ float g_htacc[20][Bg][512];
__device__ uint4 g_Wt[3 * 16 * 512];        // fused weights [j][chunk][nb*32+lane]
__device__ uint4 g_A[8192u * 32u * 32u];    // fused A quads (128 MB)
__device__ uint4 g_ghtb_hi[32u * 200u * 32u];
__device__ uint4 g_ghtb_lo[32u * 200u * 32u];
__device__ uint4 g_htw_hi[100u * 64u * 32u];
__device__ uint4 g_htw_lo[100u * 64u * 32u];

__device__ __forceinline__ uint32_t packbf(float lo, float hi) {
    uint32_t p;
    asm("cvt.rn.bf16x2.f32 %0, %1, %2;" : "=r"(p) : "f"(hi), "f"(lo));
    return p;
}
__device__ __forceinline__ void bfhl(float x, uint32_t& h16, uint32_t& l16) {
    __nv_bfloat16 hb = __float2bfloat16(x);
    float hf = __bfloat162float(hb);
    __nv_bfloat16 lb = __float2bfloat16(x - hf);
    h16 = *(const uint16_t*)&hb;
    l16 = *(const uint16_t*)&lb;
}
// pack (a at lower, b at upper) with hi/lo split
__device__ __forceinline__ void packhl(float a, float b, uint32_t& hi, uint32_t& lo) {
    uint32_t ah, al, bh, bl;
    bfhl(a, ah, al); bfhl(b, bh, bl);
    hi = ah | (bh << 16);
    lo = al | (bl << 16);
}
__device__ __forceinline__ void mma_bf16(float* d, const uint32_t* a, uint32_t b0, uint32_t b1) {
    asm volatile(
        "mma.sync.aligned.m16n8k16.row.col.f32.bf16.bf16.f32 "
        "{%0,%1,%2,%3}, {%4,%5,%6,%7}, {%8,%9}, {%0,%1,%2,%3};"
        : "+f"(d[0]), "+f"(d[1]), "+f"(d[2]), "+f"(d[3])
        : "r"(a[0]), "r"(a[1]), "r"(a[2]), "r"(a[3]), "r"(b0), "r"(b1));
}
__device__ __forceinline__ uint32_t smem_u32(const void* p) {
    uint32_t a;
    asm("{ .reg .u64 t; cvta.to.shared.u64 t, %1; cvt.u32.u64 %0, t; }" : "=r"(a) : "l"(p));
    return a;
}
__device__ __forceinline__ void cp16(uint32_t dst, const void* src) {
    asm volatile("cp.async.ca.shared.global [%0], [%1], 16;" :: "r"(dst), "l"(src));
}
#define CP_COMMIT() asm volatile("cp.async.commit_group;" ::: "memory")
#define CP_WAIT2()  asm volatile("cp.async.wait_group 2;" ::: "memory")

// ---------------- kernel 1: setup (label tables + fused weight frags) ---
__global__ void k_setup(const float* __restrict__ rel_emb,
                        const float* __restrict__ she,
                        const float* __restrict__ ste,
                        const float* __restrict__ A_w, const float* __restrict__ A_b,
                        const float* __restrict__ C_w, const float* __restrict__ C_b,
                        const float* __restrict__ E_w, const float* __restrict__ E_b)
{
    if (blockIdx.y < 5) {
        if (threadIdx.x >= 128) return;
        int r = blockIdx.x, t = blockIdx.y, d = threadIdx.x;
        const float* emb; const float* W; const float* bias = 0;
        switch (t) {
            case 0: emb = rel_emb; W = A_w + 512*128;  bias = A_b; break;
            case 1: emb = she;     W = C_w + 1536*128;             break;
            case 2: emb = she;     W = C_w + 1600*128; bias = C_b; break;
            case 3: emb = ste;     W = E_w + 1536*128;             break;
            default:emb = ste;     W = E_w + 1600*128; bias = E_b; break;
        }
        float acc = bias ? bias[d] : 0.f;
        for (int k = 0; k < 64; k++) acc += emb[r*64 + k] * W[k*128 + d];
        g_tables[t][r][d] = acc;
    } else {
        if (blockIdx.x >= 48) return;
        int c = blockIdx.x & 15;
        int j = blockIdx.x >> 4;
        const float* W = (j == 0) ? A_w : ((j == 1) ? C_w : E_w);
        uint4* dst = g_Wt + (size_t)(j*16 + c)*512;
        for (int r = 0; r < 2; r++) {
            int q = r*256 + threadIdx.x;
            int nb = q >> 5, idx = q & 31;
            int g = idx >> 2, t = idx & 3;
            int n = nb*8 + g;
            int k00 = c*32 + 2*t;
            uint4 v;
            v.x = packbf(W[(size_t)(k00 +  0)*128 + n], W[(size_t)(k00 +  1)*128 + n]);
            v.y = packbf(W[(size_t)(k00 +  8)*128 + n], W[(size_t)(k00 +  9)*128 + n]);
            v.z = packbf(W[(size_t)(k00 + 16)*128 + n], W[(size_t)(k00 + 17)*128 + n]);
            v.w = packbf(W[(size_t)(k00 + 24)*128 + n], W[(size_t)(k00 + 25)*128 + n]);
            dst[q] = v;
        }
    }
}

// ---------------- kernel 1b: bake ht_w hi/lo fragments ------------------
__global__ void k_prep_ht(const float* __restrict__ W)
{
    int c = blockIdx.x;   // chunk 0..99
    uint4* dh = g_htw_hi + (size_t)c*2048;
    uint4* dl = g_htw_lo + (size_t)c*2048;
    for (int q = threadIdx.x; q < 2048; q += 256) {
        int nb = q >> 5, idx = q & 31;
        int g = idx >> 2, t = idx & 3;
        int n = nb*8 + g;
        int k00 = c*32 + 2*t;
        uint4 vh, vl;
        packhl(W[(size_t)(k00 +  0)*512 + n], W[(size_t)(k00 +  1)*512 + n], vh.x, vl.x);
        packhl(W[(size_t)(k00 +  8)*512 + n], W[(size_t)(k00 +  9)*512 + n], vh.y, vl.y);
        packhl(W[(size_t)(k00 + 16)*512 + n], W[(size_t)(k00 + 17)*512 + n], vh.z, vl.z);
        packhl(W[(size_t)(k00 + 24)*512 + n], W[(size_t)(k00 + 25)*512 + n], vh.w, vl.w);
        dh[q] = vh;
        dl[q] = vl;
    }
}

// ---------------- kernel 2: pack fused A (single bf16, proven) ----------
__global__ void k_aprep(const float* __restrict__ flat)
{
    int G = blockIdx.x;
    #pragma unroll
    for (int r = 0; r < 4; r++) {
        int q = r*256 + threadIdx.x;
        int s = q >> 5, idx = q & 31;
        int g = idx >> 2, tt = idx & 3;
        size_t r0 = (size_t)G*16 + g, r1 = r0 + 8;
        int k0 = s*16 + 2*tt;
        float2 x  = *(const float2*)(flat + r0*512 + k0);
        float2 y  = *(const float2*)(flat + r1*512 + k0);
        float2 x8 = *(const float2*)(flat + r0*512 + k0 + 8);
        float2 y8 = *(const float2*)(flat + r1*512 + k0 + 8);
        uint4 v;
        v.x = packbf(x.x,  x.y);
        v.y = packbf(y.x,  y.y);
        v.z = packbf(x8.x, x8.y);
        v.w = packbf(y8.x, y8.y);
        g_A[((size_t)G*32 + s)*32 + idx] = v;
    }
}

// ---------------- kernel 2b: pack ght rows into hi/lo fragments ---------
__global__ void k_pack_ht()
{
    int G = blockIdx.x;   // 0..31 (16-row groups of the 512 graphs)
    const float* src = &g_ght[0][0];
    for (int q = threadIdx.x; q < 6400; q += 256) {
        int s = q >> 5, idx = q & 31;
        int g = idx >> 2, tt = idx & 3;
        size_t r0 = (size_t)G*16 + g, r1 = r0 + 8;
        int k0 = s*16 + 2*tt;
        float2 x  = *(const float2*)(src + r0*3200 + k0);
        float2 y  = *(const float2*)(src + r1*3200 + k0);
        float2 x8 = *(const float2*)(src + r0*3200 + k0 + 8);
        float2 y8 = *(const float2*)(src + r1*3200 + k0 + 8);
        uint4 vh, vl;
        packhl(x.x,  x.y,  vh.x, vl.x);
        packhl(y.x,  y.y,  vh.y, vl.y);
        packhl(x8.x, x8.y, vh.z, vl.z);
        packhl(y8.x, y8.y, vh.w, vl.w);
        size_t o = ((size_t)G*200 + s)*32 + idx;
        g_ghtb_hi[o] = vh;
        g_ghtb_lo[o] = vl;
    }
}

// ---------------- kernel 3: per-graph PG terms, split-K -----------------
__global__ __launch_bounds__(256) void k_pg(
    const float* __restrict__ flat,
    const int* __restrict__ head_ids, const int* __restrict__ tail_ids,
    const float* __restrict__ C_w, const float* __restrict__ E_w)
{
    int m0    = blockIdx.x * 32;
    int kbase = blockIdx.y * 128;
    int path  = blockIdx.z;
    const float* W = (path == 0 ? C_w : E_w) + 512*128;
    __shared__ float As[32][33];
    __shared__ float Bs[32][132];
    __shared__ int rowA[32], rowB[32];
    int tid = threadIdx.x;
    if (tid < 32) {
        int g = m0 + tid;
        int h = head_ids[g], t = tail_ids[g];
        rowA[tid] = (path == 0) ? h : t;
        rowB[tid] = (path == 0) ? t : h;
    }
    __syncthreads();
    int tx = tid & 31, ty = tid >> 5;
    float acc[4][4] = {};
    for (int kc = 0; kc < 4; kc++) {
        int k0 = kbase + kc*32;
        for (int e = tid; e < 1024; e += 256) {
            int m = e >> 5, k = e & 31;
            int kg = k0 + k;
            int row = (kg < 512) ? rowA[m] : rowB[m];
            int kk  = (kg < 512) ? kg : kg - 512;
            As[m][k] = flat[(size_t)row*512 + kk];
        }
        for (int e = tid; e < 1024; e += 256) {
            int k = e >> 5, n = (e & 31) * 4;
            *(float4*)&Bs[k][n] = *(const float4*)&W[(size_t)(k0 + k)*128 + n];
        }
        __syncthreads();
        #pragma unroll
        for (int k = 0; k < 32; k++) {
            float4 b4 = *(const float4*)&Bs[k][tx*4];
            float a[4];
            #pragma unroll
            for (int i = 0; i < 4; i++) a[i] = As[ty*4 + i][k];
            #pragma unroll
            for (int i = 0; i < 4; i++) {
                acc[i][0] += a[i]*b4.x; acc[i][1] += a[i]*b4.y;
                acc[i][2] += a[i]*b4.z; acc[i][3] += a[i]*b4.w;
            }
        }
        __syncthreads();
    }
    #pragma unroll
    for (int i = 0; i < 4; i++)
        #pragma unroll
        for (int q = 0; q < 4; q++)
            g_PGpart[blockIdx.y][path][m0 + ty*4 + i][tx*4 + q] = acc[i][q];
}

// ---------------- kernel 4: fused pipeline (round-13, proven) -----------
#define AR_OFF   0
#define BR_OFF   8192
#define SW_OFF   16384
#define SB_OFF   17920
#define PG_OFF   17936
#define WSM_OFF  18192
#define NUM_OFF  19728
#define DEN_OFF  21264
#define PRJ_OFF  21280
#define LBL_OFF  21792
#define SM_FLOATS 22176

__global__ __launch_bounds__(256, 2) void k_fused_mma(
    const float* __restrict__ flat,
    const float* __restrict__ head_sister, const float* __restrict__ tail_sister,
    const int* __restrict__ t_label, const int* __restrict__ hst, const int* __restrict__ tst,
    const float* __restrict__ B_w, const float* __restrict__ B_b,
    const float* __restrict__ Dm_w, const float* __restrict__ Dm_b,
    const float* __restrict__ G_w, const float* __restrict__ G_b,
    const int* __restrict__ head_ids, const int* __restrict__ tail_ids,
    const int* __restrict__ rel_labels,
    const float* __restrict__ she, const float* __restrict__ ste)
{
    extern __shared__ float sm[];
    const uint4* ARing = (const uint4*)(sm + AR_OFF);
    const uint4* BRing = (const uint4*)(sm + BR_OFF);
    float* SW   = sm + SW_OFF;
    float* SB   = sm + SB_OFF;
    float* PG   = sm + PG_OFF;
    float* Wsm  = sm + WSM_OFF;
    float* NUM  = sm + NUM_OFF;
    float* DEN  = sm + DEN_OFF;
    float* PRJ  = sm + PRJ_OFF;
    int*   lbl  = (int*)(sm + LBL_OFF);
    const uint32_t abase = smem_u32(sm + AR_OFF);
    const uint32_t bbase = smem_u32(sm + BR_OFF);

    const int b    = blockIdx.x;
    const int tid  = threadIdx.x;
    const int lane = tid & 31;
    const int wid  = tid >> 5;
    const int warpM = (wid & 3) * 32;
    const int warpN = (wid >> 2) * 64;
    const int qr = lane >> 2;
    const int qc = lane & 3;
    const int GlocBase = (wid & 3) * 2;
    const int nbBase   = (wid >> 2) * 8;

    for (int i = tid; i < 512; i += 256) {
        SW[i] = B_w[i]; SW[512 + i] = Dm_w[i]; SW[1024 + i] = G_w[i];
    }
    if (tid < 12) {
        int p = tid >> 2, l = tid & 3;
        SB[tid] = (p == 0) ? B_b[l] : ((p == 1) ? Dm_b[l] : G_b[l]);
        DEN[tid] = 0.f;
    }
    {
        int path = tid >> 7, col = tid & 127;
        float s = 0.f;
        #pragma unroll
        for (int q = 0; q < 8; q++) s += g_PGpart[q][path][b][col];
        PG[tid] = s;
    }
    for (int i = tid; i < 1536; i += 256) NUM[i] = 0.f;
    __syncthreads();

    const int cGl0 = tid >> 6,        cRem0 = tid & 63;
    const int cSl0 = cRem0 >> 5,      cIdx0 = cRem0 & 31;
    const int cGl1 = (256 + tid) >> 6, cRem1 = (256 + tid) & 63;
    const int cSl1 = cRem1 >> 5,      cIdx1 = cRem1 & 31;

    for (int mt = 0; mt < 2; mt++) {
        const int rowbase = b*NPG + mt*128;
        const int Gbase = rowbase >> 4;
        if (tid < 128) {
            lbl[tid]       = t_label[rowbase + tid];
            lbl[128 + tid] = hst[rowbase + tid];
            lbl[256 + tid] = tst[rowbase + tid];
        }
        __syncthreads();

        for (int j = 0; j < 3; j++) {
            float acc[2][8][4];
            #pragma unroll
            for (int mi = 0; mi < 2; mi++)
                #pragma unroll
                for (int ni = 0; ni < 8; ni++)
                    #pragma unroll
                    for (int q = 0; q < 4; q++) acc[mi][ni][q] = 0.f;

            const uint4* WjBlk = g_Wt + (size_t)j*16*512;

            #pragma unroll
            for (int pc = 0; pc < 2; pc++) {
                uint32_t ad = abase + pc*8192 + tid*16;
                uint32_t bd = bbase + pc*8192 + tid*16;
                cp16(ad,        g_A + ((size_t)(Gbase + cGl0)*32 + 2*pc + cSl0)*32 + cIdx0);
                cp16(ad + 4096, g_A + ((size_t)(Gbase + cGl1)*32 + 2*pc + cSl1)*32 + cIdx1);
                cp16(bd,        WjBlk + (size_t)pc*512 + tid);
                cp16(bd + 4096, WjBlk + (size_t)pc*512 + 256 + tid);
                CP_COMMIT();
            }

            for (int c = 0; c < 16; c++) {
                if (c + 2 < 16) {
                    int nc = c + 2, buf = nc & 3;
                    uint32_t ad = abase + buf*8192 + tid*16;
                    uint32_t bd = bbase + buf*8192 + tid*16;
                    cp16(ad,        g_A + ((size_t)(Gbase + cGl0)*32 + 2*nc + cSl0)*32 + cIdx0);
                    cp16(ad + 4096, g_A + ((size_t)(Gbase + cGl1)*32 + 2*nc + cSl1)*32 + cIdx1);
                    cp16(bd,        WjBlk + (size_t)nc*512 + tid);
                    cp16(bd + 4096, WjBlk + (size_t)nc*512 + 256 + tid);
                }
                CP_COMMIT();
                CP_WAIT2();
                __syncthreads();

                const uint4* Ab = ARing + (c & 3)*512;
                const uint4* Bb = BRing + (c & 3)*512;
                uint4 a00 = Ab[ GlocBase      *64      + lane];
                uint4 a01 = Ab[ GlocBase      *64 + 32 + lane];
                uint4 a10 = Ab[(GlocBase + 1) *64      + lane];
                uint4 a11 = Ab[(GlocBase + 1) *64 + 32 + lane];
                #pragma unroll
                for (int ni = 0; ni < 8; ni++) {
                    uint4 bv = Bb[(nbBase + ni)*32 + lane];
                    mma_bf16(acc[0][ni], (const uint32_t*)&a00, bv.x, bv.y);
                    mma_bf16(acc[0][ni], (const uint32_t*)&a01, bv.z, bv.w);
                    mma_bf16(acc[1][ni], (const uint32_t*)&a10, bv.x, bv.y);
                    mma_bf16(acc[1][ni], (const uint32_t*)&a11, bv.z, bv.w);
                }
            }
            __syncthreads();
            {
                float bvv = SB[j*4 + (tid & 3)];
                PRJ[tid]       = bvv;
                PRJ[tid + 256] = bvv;
            }
            __syncthreads();

            #pragma unroll
            for (int mi = 0; mi < 2; mi++) {
                #pragma unroll
                for (int h = 0; h < 2; h++) {
                    int r = warpM + mi*16 + qr + h*8;
                    int lT = lbl[r], lH = lbl[128 + r], lS = lbl[256 + r];
                    float p0 = 0.f, p1 = 0.f, p2 = 0.f, p3 = 0.f;
                    #pragma unroll
                    for (int ni = 0; ni < 8; ni++) {
                        int col = warpN + ni*8 + qc*2;
                        float v0 = acc[mi][ni][h*2], v1 = acc[mi][ni][h*2 + 1];
                        float add0, add1;
                        if (j == 0) {
                            float2 t = *(const float2*)&g_tables[0][lT][col];
                            add0 = t.x; add1 = t.y;
                        } else if (j == 1) {
                            float2 t1 = *(const float2*)&g_tables[1][lH][col];
                            float2 t2 = *(const float2*)&g_tables[2][lT][col];
                            add0 = PG[col] + t1.x + t2.x;
                            add1 = PG[col + 1] + t1.y + t2.y;
                        } else {
                            float2 t1 = *(const float2*)&g_tables[3][lS][col];
                            float2 t2 = *(const float2*)&g_tables[4][lT][col];
                            add0 = PG[128 + col] + t1.x + t2.x;
                            add1 = PG[128 + col + 1] + t1.y + t2.y;
                        }
                        float H0 = fmaxf(v0 + add0, 0.f);
                        float H1 = fmaxf(v1 + add1, 0.f);
                        const float* w = SW + j*512 + col*4;
                        p0 += H0*w[0] + H1*w[4];
                        p1 += H0*w[1] + H1*w[5];
                        p2 += H0*w[2] + H1*w[6];
                        p3 += H0*w[3] + H1*w[7];
                    }
                    p0 += __shfl_xor_sync(0xffffffffu, p0, 1);
                    p0 += __shfl_xor_sync(0xffffffffu, p0, 2);
                    p1 += __shfl_xor_sync(0xffffffffu, p1, 1);
                    p1 += __shfl_xor_sync(0xffffffffu, p1, 2);
                    p2 += __shfl_xor_sync(0xffffffffu, p2, 1);
                    p2 += __shfl_xor_sync(0xffffffffu, p2, 2);
                    p3 += __shfl_xor_sync(0xffffffffu, p3, 1);
                    p3 += __shfl_xor_sync(0xffffffffu, p3, 2);
                    float pl = (qc == 0) ? p0 : ((qc == 1) ? p1 : ((qc == 2) ? p2 : p3));
                    atomicAdd(&PRJ[r*4 + qc], pl);
                }
            }
            __syncthreads();
            if (tid < 128) {
                int m = tid;
                float g0 = 1.f/(1.f + expf(-PRJ[m*4 + 0]));
                float g1 = 1.f/(1.f + expf(-PRJ[m*4 + 1]));
                float g2 = 1.f/(1.f + expf(-PRJ[m*4 + 2]));
                float g3 = 1.f/(1.f + expf(-PRJ[m*4 + 3]));
                if (j == 1) {
                    const float* hsv = head_sister + (size_t)(rowbase + m)*4;
                    g0 *= hsv[0]; g1 *= hsv[1]; g2 *= hsv[2]; g3 *= hsv[3];
                } else if (j == 2) {
                    const float* tsv = tail_sister + (size_t)(rowbase + m)*4;
                    g0 *= tsv[0]; g1 *= tsv[1]; g2 *= tsv[2]; g3 *= tsv[3];
                }
                float* wp = Wsm + (size_t)(j*128 + m)*4;
                wp[0] = g0; wp[1] = g1; wp[2] = g2; wp[3] = g3;
            }
            __syncthreads();
        }

        {
            int c0 = tid, c1 = tid + 256;
            int l0 = tid >> 7, l1 = l0 + 2;
            float s00=0,s01=0,s02=0, s10=0,s11=0,s12=0;
            for (int n = 0; n < 128; n++) {
                float v0 = flat[(size_t)(rowbase + n)*512 + c0];
                float v1 = flat[(size_t)(rowbase + n)*512 + c1];
                float w0 = Wsm[(0*128+n)*4 + l0], w1 = Wsm[(1*128+n)*4 + l0], w2 = Wsm[(2*128+n)*4 + l0];
                float x0 = Wsm[(0*128+n)*4 + l1], x1 = Wsm[(1*128+n)*4 + l1], x2 = Wsm[(2*128+n)*4 + l1];
                s00 += w0*v0; s01 += w1*v0; s02 += w2*v0;
                s10 += x0*v1; s11 += x1*v1; s12 += x2*v1;
            }
            NUM[0*512 + c0] += s00; NUM[1*512 + c0] += s01; NUM[2*512 + c0] += s02;
            NUM[0*512 + c1] += s10; NUM[1*512 + c1] += s11; NUM[2*512 + c1] += s12;
            if (tid < 12) {
                int p = tid >> 2, l = tid & 3;
                float s = 0.f;
                for (int n = 0; n < 128; n++) s += Wsm[(p*128 + n)*4 + l];
                DEN[tid] += s;
            }
        }
        __syncthreads();
    }

    {
        int h = head_ids[b], t = tail_ids[b];
        int c0 = tid, c1 = tid + 256;
        int l0 = tid >> 7, l1 = l0 + 2;
        float gsum0a = NUM[0*512 + c0] / DEN[0*4 + l0];
        float gsum0b = NUM[0*512 + c1] / DEN[0*4 + l1];
        float ghsa   = NUM[1*512 + c0] / DEN[1*4 + l0];
        float ghsb   = NUM[1*512 + c1] / DEN[1*4 + l1];
        float gtsa   = NUM[2*512 + c0] / DEN[2*4 + l0];
        float gtsb   = NUM[2*512 + c1] / DEN[2*4 + l1];
        g_gsum[b][0][c0] = gsum0a; g_gsum[b][0][c1] = gsum0b;
        g_gsum[b][1][c0] = ghsa;   g_gsum[b][1][c1] = ghsb;
        g_gsum[b][2][c0] = gtsa;   g_gsum[b][2][c1] = gtsb;
        float hva = flat[(size_t)h*512 + c0], hvb = flat[(size_t)h*512 + c1];
        float tva = flat[(size_t)t*512 + c0], tvb = flat[(size_t)t*512 + c1];
        float* out = g_ght[b];
        out[c0]        = ghsa * hva;  out[c1]        = ghsb * hvb;
        out[512 + c0]  = gtsa * tva;  out[512 + c1]  = gtsb * tvb;
        out[1024 + c0] = ghsa;        out[1024 + c1] = ghsb;
        out[1536 + c0] = gtsa;        out[1536 + c1] = gtsb;
        out[2048 + c0] = hva;         out[2048 + c1] = hvb;
        out[2560 + c0] = tva;         out[2560 + c1] = tvb;
        if (tid < 64) {
            int r = rel_labels[b];
            out[3072 + tid] = she[r*64 + tid];
            out[3136 + tid] = ste[r*64 + tid];
        }
    }
}

// ---------------- kernel 5: ht GEMM via 3-pass bf16 hi/lo, split-K 20 ---
__global__ __launch_bounds__(256) void k_ht_mma()
{
    const int tid  = threadIdx.x;
    const int lane = tid & 31;
    const int wid  = tid >> 5;
    const int warpM = (wid & 3) * 32;
    const int warpN = (wid >> 2) * 64;
    const int qr = lane >> 2;
    const int qc = lane & 3;
    const int Gbase = blockIdx.y*8 + (wid & 3)*2;
    const int nbB   = blockIdx.x*16 + (wid >> 2)*8;
    const int c0k   = blockIdx.z*5;

    float acc[2][8][4];
    #pragma unroll
    for (int mi = 0; mi < 2; mi++)
        #pragma unroll
        for (int ni = 0; ni < 8; ni++)
            #pragma unroll
            for (int q = 0; q < 4; q++) acc[mi][ni][q] = 0.f;

    for (int c = 0; c < 5; c++) {
        int chunk = c0k + c;
        size_t aoff0 = ((size_t)Gbase*200 + 2*chunk)*32 + lane;
        size_t aoff1 = ((size_t)(Gbase + 1)*200 + 2*chunk)*32 + lane;
        uint4 a00h = g_ghtb_hi[aoff0],      a01h = g_ghtb_hi[aoff0 + 32];
        uint4 a10h = g_ghtb_hi[aoff1],      a11h = g_ghtb_hi[aoff1 + 32];
        uint4 a00l = g_ghtb_lo[aoff0],      a01l = g_ghtb_lo[aoff0 + 32];
        uint4 a10l = g_ghtb_lo[aoff1],      a11l = g_ghtb_lo[aoff1 + 32];
        size_t woff = (size_t)chunk*2048 + (size_t)nbB*32 + lane;
        #pragma unroll
        for (int ni = 0; ni < 8; ni++) {
            uint4 bh = g_htw_hi[woff + ni*32];
            uint4 bl = g_htw_lo[woff + ni*32];
            // s = 0
            mma_bf16(acc[0][ni], (const uint32_t*)&a00h, bh.x, bh.y);
            mma_bf16(acc[0][ni], (const uint32_t*)&a00l, bh.x, bh.y);
            mma_bf16(acc[0][ni], (const uint32_t*)&a00h, bl.x, bl.y);
            mma_bf16(acc[1][ni], (const uint32_t*)&a10h, bh.x, bh.y);
            mma_bf16(acc[1][ni], (const uint32_t*)&a10l, bh.x, bh.y);
            mma_bf16(acc[1][ni], (const uint32_t*)&a10h, bl.x, bl.y);
            // s = 1
            mma_bf16(acc[0][ni], (const uint32_t*)&a01h, bh.z, bh.w);
            mma_bf16(acc[0][ni], (const uint32_t*)&a01l, bh.z, bh.w);
            mma_bf16(acc[0][ni], (const uint32_t*)&a01h, bl.z, bl.w);
            mma_bf16(acc[1][ni], (const uint32_t*)&a11h, bh.z, bh.w);
            mma_bf16(acc[1][ni], (const uint32_t*)&a11l, bh.z, bh.w);
            mma_bf16(acc[1][ni], (const uint32_t*)&a11h, bl.z, bl.w);
        }
    }

    float* dst = &g_htacc[blockIdx.z][0][0];
    #pragma unroll
    for (int mi = 0; mi < 2; mi++)
        #pragma unroll
        for (int h = 0; h < 2; h++) {
            int m = blockIdx.y*128 + warpM + mi*16 + qr + h*8;
            #pragma unroll
            for (int ni = 0; ni < 8; ni++) {
                int n = blockIdx.x*128 + warpN + ni*8 + qc*2;
                *(float2*)(dst + (size_t)m*512 + n) =
                    make_float2(acc[mi][ni][h*2], acc[mi][ni][h*2 + 1]);
            }
        }
}

// ---------------- kernel 6: fc + out -------------------------------------
__global__ void k_final(const float* __restrict__ flat,
                        const int* __restrict__ head_ids, const int* __restrict__ tail_ids,
                        const int* __restrict__ rel_labels, const float* __restrict__ rel_emb,
                        const float* __restrict__ ht_b,
                        const float* __restrict__ fc_w, const float* __restrict__ fc_b,
                        const float* __restrict__ out_w, const float* __restrict__ out_b,
                        float* __restrict__ out)
{
    __shared__ float rep[2112];
    __shared__ float red[256][17];
    int b = blockIdx.x, tid = threadIdx.x;
    int h = head_ids[b], t = tail_ids[b];
    for (int c = tid; c < 512; c += 256) {
        rep[c]        = g_gsum[b][0][c];
        rep[512 + c]  = flat[(size_t)h*512 + c];
        rep[1024 + c] = flat[(size_t)t*512 + c];
        float s = 0.f;
        #pragma unroll
        for (int q = 0; q < 20; q++) s += g_htacc[q][b][c];
        rep[1536 + c] = fmaxf(s + ht_b[c], 0.f);
    }
    if (tid < 64) rep[2048 + tid] = rel_emb[rel_labels[b]*64 + tid];
    __syncthreads();

    float acc[16];
    #pragma unroll
    for (int j = 0; j < 16; j++) acc[j] = 0.f;
    for (int k = tid; k < 2112; k += 256) {
        float x = rep[k];
        const float4* w = (const float4*)(fc_w + (size_t)k*16);
        #pragma unroll
        for (int v = 0; v < 4; v++) {
            float4 ww = w[v];
            acc[v*4+0] += x*ww.x; acc[v*4+1] += x*ww.y;
            acc[v*4+2] += x*ww.z; acc[v*4+3] += x*ww.w;
        }
    }
    #pragma unroll
    for (int j = 0; j < 16; j++) red[tid][j] = acc[j];
    __syncthreads();
    for (int s = 128; s >= 1; s >>= 1) {
        if (tid < s) {
            #pragma unroll
            for (int j = 0; j < 16; j++) red[tid][j] += red[tid + s][j];
        }
        __syncthreads();
    }
    if (tid == 0) {
        float o = out_b[0];
        #pragma unroll
        for (int j = 0; j < 16; j++) o += fmaxf(red[0][j] + fc_b[j], 0.f) * out_w[j];
        out[b] = o;
    }
}

// ---------------- launch ------------------------------------------------
extern "C" void kernel_launch(void* const* d_in, const int* in_sizes, int n_in,
                              void* d_out, int out_size)
{
    const float* node_repr = (const float*)d_in[0];
    const float* head_sis  = (const float*)d_in[1];
    const float* tail_sis  = (const float*)d_in[2];
    const int*   t_label   = (const int*)d_in[3];
    const int*   hstp      = (const int*)d_in[4];
    const int*   tstp      = (const int*)d_in[5];
    const int*   head_ids  = (const int*)d_in[7];
    const int*   tail_ids  = (const int*)d_in[8];
    const int*   rel_lab   = (const int*)d_in[9];
    const float* rel_emb   = (const float*)d_in[10];
    const float* she       = (const float*)d_in[11];
    const float* ste       = (const float*)d_in[12];
    const float* A_w  = (const float*)d_in[13]; const float* A_b  = (const float*)d_in[14];
    const float* B_w  = (const float*)d_in[15]; const float* B_b  = (const float*)d_in[16];
    const float* C_w  = (const float*)d_in[17]; const float* C_b  = (const float*)d_in[18];
    const float* Dm_w = (const float*)d_in[19]; const float* Dm_b = (const float*)d_in[20];
    const float* E_w  = (const float*)d_in[21]; const float* E_b  = (const float*)d_in[22];
    const float* G_w  = (const float*)d_in[23]; const float* G_b  = (const float*)d_in[24];
    const float* ht_w = (const float*)d_in[25]; const float* ht_b = (const float*)d_in[26];
    const float* fc_w = (const float*)d_in[27]; const float* fc_b = (const float*)d_in[28];
    const float* out_w= (const float*)d_in[29]; const float* out_b= (const float*)d_in[30];
    float* out = (float*)d_out;

    const int smemBytes = SM_FLOATS * 4;
    cudaFuncSetAttribute(k_fused_mma, cudaFuncAttributeMaxDynamicSharedMemorySize, smemBytes);

    k_setup<<<dim3(Rr, 6), 256>>>(rel_emb, she, ste, A_w, A_b, C_w, C_b, E_w, E_b);
    k_prep_ht<<<100, 256>>>(ht_w);
    k_aprep<<<8192, 256>>>(node_repr);
    k_pg<<<dim3(16, 8, 2), 256>>>(node_repr, head_ids, tail_ids, C_w, E_w);
    k_fused_mma<<<Bg, 256, smemBytes>>>(node_repr, head_sis, tail_sis, t_label, hstp, tstp,
                                        B_w, B_b, Dm_w, Dm_b, G_w, G_b,
                                        head_ids, tail_ids, rel_lab, she, ste);
    k_pack_ht<<<32, 256>>>();
    k_ht_mma<<<dim3(4, 4, 20), 256>>>();
    k_final<<<Bg, 256>>>(node_repr, head_ids, tail_ids, rel_lab, rel_emb, ht_b,
                         fc_w, fc_b, out_w, out_b, out);
}

// round 17
// speedup vs baseline: 1.0996x; 1.0279x over previous
#include <cuda_runtime.h>
#include <math.h>
#include <stdint.h>

#define Bg   512
#define NPG  256
#define Rr   51

// ---------------- device scratch ----------------
__device__ float g_tables[5][Rr][128];
__device__ float g_PGpart[8][2][Bg][128];
__device__ float g_gsum[Bg][3][512];
__device__ float g_ght[Bg][3200];
__device__ float g_htacc[10][Bg][512];
__device__ uint4 g_Wt[3 * 16 * 512];       // [j][chunk][nb*32 + lane] b-frag quads
__device__ uint4 g_A[8192u * 32u * 32u];   // [G][s][lane] a-frag quads (128 MB)

__device__ __forceinline__ uint32_t packbf(float lo, float hi) {
    uint32_t p;
    asm("cvt.rn.bf16x2.f32 %0, %1, %2;" : "=r"(p) : "f"(hi), "f"(lo));
    return p;
}
__device__ __forceinline__ void mma_bf16(float* d, const uint32_t* a, uint32_t b0, uint32_t b1) {
    asm volatile(
        "mma.sync.aligned.m16n8k16.row.col.f32.bf16.bf16.f32 "
        "{%0,%1,%2,%3}, {%4,%5,%6,%7}, {%8,%9}, {%0,%1,%2,%3};"
        : "+f"(d[0]), "+f"(d[1]), "+f"(d[2]), "+f"(d[3])
        : "r"(a[0]), "r"(a[1]), "r"(a[2]), "r"(a[3]), "r"(b0), "r"(b1));
}
__device__ __forceinline__ uint32_t smem_u32(const void* p) {
    uint32_t a;
    asm("{ .reg .u64 t; cvta.to.shared.u64 t, %1; cvt.u32.u64 %0, t; }" : "=r"(a) : "l"(p));
    return a;
}
__device__ __forceinline__ void cp16(uint32_t dst, const void* src) {
    asm volatile("cp.async.ca.shared.global [%0], [%1], 16;" :: "r"(dst), "l"(src));
}
#define CP_COMMIT() asm volatile("cp.async.commit_group;" ::: "memory")
#define CP_WAIT2()  asm volatile("cp.async.wait_group 2;" ::: "memory")

// ---------------- kernel 1: merged front (aprep | pg | tables | wbake) --
// grid: [0,8192) aprep, [8192,8448) pg, [8448,8703) tables, [8703,8751) wbake
__global__ __launch_bounds__(256) void k_front(
    const float* __restrict__ flat,
    const int* __restrict__ head_ids, const int* __restrict__ tail_ids,
    const float* __restrict__ rel_emb, const float* __restrict__ she,
    const float* __restrict__ ste,
    const float* __restrict__ A_w, const float* __restrict__ A_b,
    const float* __restrict__ C_w, const float* __restrict__ C_b,
    const float* __restrict__ E_w, const float* __restrict__ E_b)
{
    __shared__ float As[32][33];
    __shared__ float Bs[32][132];
    __shared__ int rowA[32], rowB[32];

    const int bid = blockIdx.x;
    const int tid = threadIdx.x;

    if (bid < 8192) {
        // ---- aprep: stage A rows into bf16 fragment quads ----
        int G = bid;
        #pragma unroll
        for (int r = 0; r < 4; r++) {
            int q = r*256 + tid;
            int s = q >> 5, idx = q & 31;
            int g = idx >> 2, tt = idx & 3;
            size_t r0 = (size_t)G*16 + g, r1 = r0 + 8;
            int k0 = s*16 + 2*tt;
            float2 x  = *(const float2*)(flat + r0*512 + k0);
            float2 y  = *(const float2*)(flat + r1*512 + k0);
            float2 x8 = *(const float2*)(flat + r0*512 + k0 + 8);
            float2 y8 = *(const float2*)(flat + r1*512 + k0 + 8);
            uint4 v;
            v.x = packbf(x.x,  x.y);
            v.y = packbf(y.x,  y.y);
            v.z = packbf(x8.x, x8.y);
            v.w = packbf(y8.x, y8.y);
            g_A[((size_t)G*32 + s)*32 + idx] = v;
        }
    } else if (bid < 8448) {
        // ---- pg: per-graph PG partials, split-K ----
        int idx   = bid - 8192;
        int m0    = (idx & 15) * 32;
        int ksl   = (idx >> 4) & 7;
        int path  = idx >> 7;
        int kbase = ksl * 128;
        const float* W = (path == 0 ? C_w : E_w) + 512*128;
        if (tid < 32) {
            int g = m0 + tid;
            int h = head_ids[g], t = tail_ids[g];
            rowA[tid] = (path == 0) ? h : t;
            rowB[tid] = (path == 0) ? t : h;
        }
        __syncthreads();
        int tx = tid & 31, ty = tid >> 5;
        float acc[4][4] = {};
        for (int kc = 0; kc < 4; kc++) {
            int k0 = kbase + kc*32;
            for (int e = tid; e < 1024; e += 256) {
                int m = e >> 5, k = e & 31;
                int kg = k0 + k;
                int row = (kg < 512) ? rowA[m] : rowB[m];
                int kk  = (kg < 512) ? kg : kg - 512;
                As[m][k] = flat[(size_t)row*512 + kk];
            }
            for (int e = tid; e < 1024; e += 256) {
                int k = e >> 5, n = (e & 31) * 4;
                *(float4*)&Bs[k][n] = *(const float4*)&W[(size_t)(k0 + k)*128 + n];
            }
            __syncthreads();
            #pragma unroll
            for (int k = 0; k < 32; k++) {
                float4 b4 = *(const float4*)&Bs[k][tx*4];
                float a[4];
                #pragma unroll
                for (int i = 0; i < 4; i++) a[i] = As[ty*4 + i][k];
                #pragma unroll
                for (int i = 0; i < 4; i++) {
                    acc[i][0] += a[i]*b4.x; acc[i][1] += a[i]*b4.y;
                    acc[i][2] += a[i]*b4.z; acc[i][3] += a[i]*b4.w;
                }
            }
            __syncthreads();
        }
        #pragma unroll
        for (int i = 0; i < 4; i++)
            #pragma unroll
            for (int q = 0; q < 4; q++)
                g_PGpart[ksl][path][m0 + ty*4 + i][tx*4 + q] = acc[i][q];
    } else if (bid < 8703) {
        // ---- label tables ----
        if (tid >= 128) return;
        int idx = bid - 8448;
        int r = idx % Rr, t = idx / Rr;
        const float* emb; const float* W; const float* bias = 0;
        switch (t) {
            case 0: emb = rel_emb; W = A_w + 512*128;  bias = A_b; break;
            case 1: emb = she;     W = C_w + 1536*128;             break;
            case 2: emb = she;     W = C_w + 1600*128; bias = C_b; break;
            case 3: emb = ste;     W = E_w + 1536*128;             break;
            default:emb = ste;     W = E_w + 1600*128; bias = E_b; break;
        }
        float acc = bias ? bias[tid] : 0.f;
        for (int k = 0; k < 64; k++) acc += emb[r*64 + k] * W[k*128 + tid];
        g_tables[t][r][tid] = acc;
    } else {
        // ---- bake fused weight fragments ----
        int idx = bid - 8703;            // 0..47
        int c = idx & 15;
        int j = idx >> 4;
        const float* W = (j == 0) ? A_w : ((j == 1) ? C_w : E_w);
        uint4* dst = g_Wt + (size_t)(j*16 + c)*512;
        for (int r = 0; r < 2; r++) {
            int q = r*256 + tid;
            int nb = q >> 5, qidx = q & 31;
            int g = qidx >> 2, t = qidx & 3;
            int n = nb*8 + g;
            int k00 = c*32 + 2*t;
            uint4 v;
            v.x = packbf(W[(size_t)(k00 +  0)*128 + n], W[(size_t)(k00 +  1)*128 + n]);
            v.y = packbf(W[(size_t)(k00 +  8)*128 + n], W[(size_t)(k00 +  9)*128 + n]);
            v.z = packbf(W[(size_t)(k00 + 16)*128 + n], W[(size_t)(k00 + 17)*128 + n]);
            v.w = packbf(W[(size_t)(k00 + 24)*128 + n], W[(size_t)(k00 + 25)*128 + n]);
            dst[q] = v;
        }
    }
}

// ---------------- kernel 2: fused pipeline (round-13, proven 333us) -----
#define AR_OFF   0
#define BR_OFF   8192
#define SW_OFF   16384
#define SB_OFF   17920
#define PG_OFF   17936
#define WSM_OFF  18192
#define NUM_OFF  19728
#define DEN_OFF  21264
#define PRJ_OFF  21280
#define LBL_OFF  21792
#define SM_FLOATS 22176

__global__ __launch_bounds__(256, 2) void k_fused_mma(
    const float* __restrict__ flat,
    const float* __restrict__ head_sister, const float* __restrict__ tail_sister,
    const int* __restrict__ t_label, const int* __restrict__ hst, const int* __restrict__ tst,
    const float* __restrict__ B_w, const float* __restrict__ B_b,
    const float* __restrict__ Dm_w, const float* __restrict__ Dm_b,
    const float* __restrict__ G_w, const float* __restrict__ G_b,
    const int* __restrict__ head_ids, const int* __restrict__ tail_ids,
    const int* __restrict__ rel_labels,
    const float* __restrict__ she, const float* __restrict__ ste)
{
    extern __shared__ float sm[];
    const uint4* ARing = (const uint4*)(sm + AR_OFF);
    const uint4* BRing = (const uint4*)(sm + BR_OFF);
    float* SW   = sm + SW_OFF;
    float* SB   = sm + SB_OFF;
    float* PG   = sm + PG_OFF;
    float* Wsm  = sm + WSM_OFF;
    float* NUM  = sm + NUM_OFF;
    float* DEN  = sm + DEN_OFF;
    float* PRJ  = sm + PRJ_OFF;
    int*   lbl  = (int*)(sm + LBL_OFF);
    const uint32_t abase = smem_u32(sm + AR_OFF);
    const uint32_t bbase = smem_u32(sm + BR_OFF);

    const int b    = blockIdx.x;
    const int tid  = threadIdx.x;
    const int lane = tid & 31;
    const int wid  = tid >> 5;
    const int warpM = (wid & 3) * 32;
    const int warpN = (wid >> 2) * 64;
    const int qr = lane >> 2;
    const int qc = lane & 3;
    const int GlocBase = (wid & 3) * 2;
    const int nbBase   = (wid >> 2) * 8;

    for (int i = tid; i < 512; i += 256) {
        SW[i] = B_w[i]; SW[512 + i] = Dm_w[i]; SW[1024 + i] = G_w[i];
    }
    if (tid < 12) {
        int p = tid >> 2, l = tid & 3;
        SB[tid] = (p == 0) ? B_b[l] : ((p == 1) ? Dm_b[l] : G_b[l]);
        DEN[tid] = 0.f;
    }
    {
        int path = tid >> 7, col = tid & 127;
        float s = 0.f;
        #pragma unroll
        for (int q = 0; q < 8; q++) s += g_PGpart[q][path][b][col];
        PG[tid] = s;
    }
    for (int i = tid; i < 1536; i += 256) NUM[i] = 0.f;
    __syncthreads();

    const int cGl0 = tid >> 6,        cRem0 = tid & 63;
    const int cSl0 = cRem0 >> 5,      cIdx0 = cRem0 & 31;
    const int cGl1 = (256 + tid) >> 6, cRem1 = (256 + tid) & 63;
    const int cSl1 = cRem1 >> 5,      cIdx1 = cRem1 & 31;

    for (int mt = 0; mt < 2; mt++) {
        const int rowbase = b*NPG + mt*128;
        const int Gbase = rowbase >> 4;
        if (tid < 128) {
            lbl[tid]       = t_label[rowbase + tid];
            lbl[128 + tid] = hst[rowbase + tid];
            lbl[256 + tid] = tst[rowbase + tid];
        }
        __syncthreads();

        for (int j = 0; j < 3; j++) {
            float acc[2][8][4];
            #pragma unroll
            for (int mi = 0; mi < 2; mi++)
                #pragma unroll
                for (int ni = 0; ni < 8; ni++)
                    #pragma unroll
                    for (int q = 0; q < 4; q++) acc[mi][ni][q] = 0.f;

            const uint4* WjBlk = g_Wt + (size_t)j*16*512;

            #pragma unroll
            for (int pc = 0; pc < 2; pc++) {
                uint32_t ad = abase + pc*8192 + tid*16;
                uint32_t bd = bbase + pc*8192 + tid*16;
                cp16(ad,        g_A + ((size_t)(Gbase + cGl0)*32 + 2*pc + cSl0)*32 + cIdx0);
                cp16(ad + 4096, g_A + ((size_t)(Gbase + cGl1)*32 + 2*pc + cSl1)*32 + cIdx1);
                cp16(bd,        WjBlk + (size_t)pc*512 + tid);
                cp16(bd + 4096, WjBlk + (size_t)pc*512 + 256 + tid);
                CP_COMMIT();
            }

            for (int c = 0; c < 16; c++) {
                if (c + 2 < 16) {
                    int nc = c + 2, buf = nc & 3;
                    uint32_t ad = abase + buf*8192 + tid*16;
                    uint32_t bd = bbase + buf*8192 + tid*16;
                    cp16(ad,        g_A + ((size_t)(Gbase + cGl0)*32 + 2*nc + cSl0)*32 + cIdx0);
                    cp16(ad + 4096, g_A + ((size_t)(Gbase + cGl1)*32 + 2*nc + cSl1)*32 + cIdx1);
                    cp16(bd,        WjBlk + (size_t)nc*512 + tid);
                    cp16(bd + 4096, WjBlk + (size_t)nc*512 + 256 + tid);
                }
                CP_COMMIT();
                CP_WAIT2();
                __syncthreads();

                const uint4* Ab = ARing + (c & 3)*512;
                const uint4* Bb = BRing + (c & 3)*512;
                uint4 a00 = Ab[ GlocBase      *64      + lane];
                uint4 a01 = Ab[ GlocBase      *64 + 32 + lane];
                uint4 a10 = Ab[(GlocBase + 1) *64      + lane];
                uint4 a11 = Ab[(GlocBase + 1) *64 + 32 + lane];
                #pragma unroll
                for (int ni = 0; ni < 8; ni++) {
                    uint4 bv = Bb[(nbBase + ni)*32 + lane];
                    mma_bf16(acc[0][ni], (const uint32_t*)&a00, bv.x, bv.y);
                    mma_bf16(acc[0][ni], (const uint32_t*)&a01, bv.z, bv.w);
                    mma_bf16(acc[1][ni], (const uint32_t*)&a10, bv.x, bv.y);
                    mma_bf16(acc[1][ni], (const uint32_t*)&a11, bv.z, bv.w);
                }
            }
            __syncthreads();
            {
                float bvv = SB[j*4 + (tid & 3)];
                PRJ[tid]       = bvv;
                PRJ[tid + 256] = bvv;
            }
            __syncthreads();

            #pragma unroll
            for (int mi = 0; mi < 2; mi++) {
                #pragma unroll
                for (int h = 0; h < 2; h++) {
                    int r = warpM + mi*16 + qr + h*8;
                    int lT = lbl[r], lH = lbl[128 + r], lS = lbl[256 + r];
                    float p0 = 0.f, p1 = 0.f, p2 = 0.f, p3 = 0.f;
                    #pragma unroll
                    for (int ni = 0; ni < 8; ni++) {
                        int col = warpN + ni*8 + qc*2;
                        float v0 = acc[mi][ni][h*2], v1 = acc[mi][ni][h*2 + 1];
                        float add0, add1;
                        if (j == 0) {
                            float2 t = *(const float2*)&g_tables[0][lT][col];
                            add0 = t.x; add1 = t.y;
                        } else if (j == 1) {
                            float2 t1 = *(const float2*)&g_tables[1][lH][col];
                            float2 t2 = *(const float2*)&g_tables[2][lT][col];
                            add0 = PG[col] + t1.x + t2.x;
                            add1 = PG[col + 1] + t1.y + t2.y;
                        } else {
                            float2 t1 = *(const float2*)&g_tables[3][lS][col];
                            float2 t2 = *(const float2*)&g_tables[4][lT][col];
                            add0 = PG[128 + col] + t1.x + t2.x;
                            add1 = PG[128 + col + 1] + t1.y + t2.y;
                        }
                        float H0 = fmaxf(v0 + add0, 0.f);
                        float H1 = fmaxf(v1 + add1, 0.f);
                        const float* w = SW + j*512 + col*4;
                        p0 += H0*w[0] + H1*w[4];
                        p1 += H0*w[1] + H1*w[5];
                        p2 += H0*w[2] + H1*w[6];
                        p3 += H0*w[3] + H1*w[7];
                    }
                    p0 += __shfl_xor_sync(0xffffffffu, p0, 1);
                    p0 += __shfl_xor_sync(0xffffffffu, p0, 2);
                    p1 += __shfl_xor_sync(0xffffffffu, p1, 1);
                    p1 += __shfl_xor_sync(0xffffffffu, p1, 2);
                    p2 += __shfl_xor_sync(0xffffffffu, p2, 1);
                    p2 += __shfl_xor_sync(0xffffffffu, p2, 2);
                    p3 += __shfl_xor_sync(0xffffffffu, p3, 1);
                    p3 += __shfl_xor_sync(0xffffffffu, p3, 2);
                    float pl = (qc == 0) ? p0 : ((qc == 1) ? p1 : ((qc == 2) ? p2 : p3));
                    atomicAdd(&PRJ[r*4 + qc], pl);
                }
            }
            __syncthreads();
            if (tid < 128) {
                int m = tid;
                float g0 = 1.f/(1.f + expf(-PRJ[m*4 + 0]));
                float g1 = 1.f/(1.f + expf(-PRJ[m*4 + 1]));
                float g2 = 1.f/(1.f + expf(-PRJ[m*4 + 2]));
                float g3 = 1.f/(1.f + expf(-PRJ[m*4 + 3]));
                if (j == 1) {
                    const float* hsv = head_sister + (size_t)(rowbase + m)*4;
                    g0 *= hsv[0]; g1 *= hsv[1]; g2 *= hsv[2]; g3 *= hsv[3];
                } else if (j == 2) {
                    const float* tsv = tail_sister + (size_t)(rowbase + m)*4;
                    g0 *= tsv[0]; g1 *= tsv[1]; g2 *= tsv[2]; g3 *= tsv[3];
                }
                float* wp = Wsm + (size_t)(j*128 + m)*4;
                wp[0] = g0; wp[1] = g1; wp[2] = g2; wp[3] = g3;
            }
            __syncthreads();
        }

        {
            int c0 = tid, c1 = tid + 256;
            int l0 = tid >> 7, l1 = l0 + 2;
            float s00=0,s01=0,s02=0, s10=0,s11=0,s12=0;
            for (int n = 0; n < 128; n++) {
                float v0 = flat[(size_t)(rowbase + n)*512 + c0];
                float v1 = flat[(size_t)(rowbase + n)*512 + c1];
                float w0 = Wsm[(0*128+n)*4 + l0], w1 = Wsm[(1*128+n)*4 + l0], w2 = Wsm[(2*128+n)*4 + l0];
                float x0 = Wsm[(0*128+n)*4 + l1], x1 = Wsm[(1*128+n)*4 + l1], x2 = Wsm[(2*128+n)*4 + l1];
                s00 += w0*v0; s01 += w1*v0; s02 += w2*v0;
                s10 += x0*v1; s11 += x1*v1; s12 += x2*v1;
            }
            NUM[0*512 + c0] += s00; NUM[1*512 + c0] += s01; NUM[2*512 + c0] += s02;
            NUM[0*512 + c1] += s10; NUM[1*512 + c1] += s11; NUM[2*512 + c1] += s12;
            if (tid < 12) {
                int p = tid >> 2, l = tid & 3;
                float s = 0.f;
                for (int n = 0; n < 128; n++) s += Wsm[(p*128 + n)*4 + l];
                DEN[tid] += s;
            }
        }
        __syncthreads();
    }

    {
        int h = head_ids[b], t = tail_ids[b];
        int c0 = tid, c1 = tid + 256;
        int l0 = tid >> 7, l1 = l0 + 2;
        float gsum0a = NUM[0*512 + c0] / DEN[0*4 + l0];
        float gsum0b = NUM[0*512 + c1] / DEN[0*4 + l1];
        float ghsa   = NUM[1*512 + c0] / DEN[1*4 + l0];
        float ghsb   = NUM[1*512 + c1] / DEN[1*4 + l1];
        float gtsa   = NUM[2*512 + c0] / DEN[2*4 + l0];
        float gtsb   = NUM[2*512 + c1] / DEN[2*4 + l1];
        g_gsum[b][0][c0] = gsum0a; g_gsum[b][0][c1] = gsum0b;
        g_gsum[b][1][c0] = ghsa;   g_gsum[b][1][c1] = ghsb;
        g_gsum[b][2][c0] = gtsa;   g_gsum[b][2][c1] = gtsb;
        float hva = flat[(size_t)h*512 + c0], hvb = flat[(size_t)h*512 + c1];
        float tva = flat[(size_t)t*512 + c0], tvb = flat[(size_t)t*512 + c1];
        float* out = g_ght[b];
        out[c0]        = ghsa * hva;  out[c1]        = ghsb * hvb;
        out[512 + c0]  = gtsa * tva;  out[512 + c1]  = gtsb * tvb;
        out[1024 + c0] = ghsa;        out[1024 + c1] = ghsb;
        out[1536 + c0] = gtsa;        out[1536 + c1] = gtsb;
        out[2048 + c0] = hva;         out[2048 + c1] = hvb;
        out[2560 + c0] = tva;         out[2560 + c1] = tvb;
        if (tid < 64) {
            int r = rel_labels[b];
            out[3072 + tid] = she[r*64 + tid];
            out[3136 + tid] = ste[r*64 + tid];
        }
    }
}

// ---------------- kernel 3: ht GEMM split-K 10 (fp32, proven) -----------
__global__ __launch_bounds__(256) void k_ht(const float* __restrict__ ht_w)
{
    __shared__ float As2[64][33], Bs2[32][65];
    int m0 = blockIdx.y*64, n0 = blockIdx.x*64, kbase = blockIdx.z*320;
    int tid = threadIdx.x, tx = tid & 15, ty = tid >> 4;
    float acc[4][4] = {};
    for (int kc = 0; kc < 10; kc++) {
        int k0 = kbase + kc*32;
        #pragma unroll
        for (int r = 0; r < 8; r++) {
            int e = r*256 + tid; int m = e >> 5, k = e & 31;
            As2[m][k] = g_ght[m0 + m][k0 + k];
        }
        #pragma unroll
        for (int r = 0; r < 8; r++) {
            int e = r*256 + tid; int k = e >> 6, n = e & 63;
            Bs2[k][n] = ht_w[(size_t)(k0 + k)*512 + n0 + n];
        }
        __syncthreads();
        #pragma unroll
        for (int k = 0; k < 32; k++) {
            float a[4], bv[4];
            #pragma unroll
            for (int i = 0; i < 4; i++) { a[i] = As2[ty*4 + i][k]; bv[i] = Bs2[k][tx*4 + i]; }
            #pragma unroll
            for (int i = 0; i < 4; i++)
                #pragma unroll
                for (int q = 0; q < 4; q++) acc[i][q] += a[i]*bv[q];
        }
        __syncthreads();
    }
    #pragma unroll
    for (int i = 0; i < 4; i++)
        #pragma unroll
        for (int q = 0; q < 4; q++)
            g_htacc[blockIdx.z][m0 + ty*4 + i][n0 + tx*4 + q] = acc[i][q];
}

// ---------------- kernel 4: fc + out -------------------------------------
__global__ void k_final(const float* __restrict__ flat,
                        const int* __restrict__ head_ids, const int* __restrict__ tail_ids,
                        const int* __restrict__ rel_labels, const float* __restrict__ rel_emb,
                        const float* __restrict__ ht_b,
                        const float* __restrict__ fc_w, const float* __restrict__ fc_b,
                        const float* __restrict__ out_w, const float* __restrict__ out_b,
                        float* __restrict__ out)
{
    __shared__ float rep[2112];
    __shared__ float red[256][17];
    int b = blockIdx.x, tid = threadIdx.x;
    int h = head_ids[b], t = tail_ids[b];
    for (int c = tid; c < 512; c += 256) {
        rep[c]        = g_gsum[b][0][c];
        rep[512 + c]  = flat[(size_t)h*512 + c];
        rep[1024 + c] = flat[(size_t)t*512 + c];
        float s = 0.f;
        #pragma unroll
        for (int q = 0; q < 10; q++) s += g_htacc[q][b][c];
        rep[1536 + c] = fmaxf(s + ht_b[c], 0.f);
    }
    if (tid < 64) rep[2048 + tid] = rel_emb[rel_labels[b]*64 + tid];
    __syncthreads();

    float acc[16];
    #pragma unroll
    for (int j = 0; j < 16; j++) acc[j] = 0.f;
    for (int k = tid; k < 2112; k += 256) {
        float x = rep[k];
        const float4* w = (const float4*)(fc_w + (size_t)k*16);
        #pragma unroll
        for (int v = 0; v < 4; v++) {
            float4 ww = w[v];
            acc[v*4+0] += x*ww.x; acc[v*4+1] += x*ww.y;
            acc[v*4+2] += x*ww.z; acc[v*4+3] += x*ww.w;
        }
    }
    #pragma unroll
    for (int j = 0; j < 16; j++) red[tid][j] = acc[j];
    __syncthreads();
    for (int s = 128; s >= 1; s >>= 1) {
        if (tid < s) {
            #pragma unroll
            for (int j = 0; j < 16; j++) red[tid][j] += red[tid + s][j];
        }
        __syncthreads();
    }
    if (tid == 0) {
        float o = out_b[0];
        #pragma unroll
        for (int j = 0; j < 16; j++) o += fmaxf(red[0][j] + fc_b[j], 0.f) * out_w[j];
        out[b] = o;
    }
}

// ---------------- launch ------------------------------------------------
extern "C" void kernel_launch(void* const* d_in, const int* in_sizes, int n_in,
                              void* d_out, int out_size)
{
    const float* node_repr = (const float*)d_in[0];
    const float* head_sis  = (const float*)d_in[1];
    const float* tail_sis  = (const float*)d_in[2];
    const int*   t_label   = (const int*)d_in[3];
    const int*   hstp      = (const int*)d_in[4];
    const int*   tstp      = (const int*)d_in[5];
    const int*   head_ids  = (const int*)d_in[7];
    const int*   tail_ids  = (const int*)d_in[8];
    const int*   rel_lab   = (const int*)d_in[9];
    const float* rel_emb   = (const float*)d_in[10];
    const float* she       = (const float*)d_in[11];
    const float* ste       = (const float*)d_in[12];
    const float* A_w  = (const float*)d_in[13]; const float* A_b  = (const float*)d_in[14];
    const float* B_w  = (const float*)d_in[15]; const float* B_b  = (const float*)d_in[16];
    const float* C_w  = (const float*)d_in[17]; const float* C_b  = (const float*)d_in[18];
    const float* Dm_w = (const float*)d_in[19]; const float* Dm_b = (const float*)d_in[20];
    const float* E_w  = (const float*)d_in[21]; const float* E_b  = (const float*)d_in[22];
    const float* G_w  = (const float*)d_in[23]; const float* G_b  = (const float*)d_in[24];
    const float* ht_w = (const float*)d_in[25]; const float* ht_b = (const float*)d_in[26];
    const float* fc_w = (const float*)d_in[27]; const float* fc_b = (const float*)d_in[28];
    const float* out_w= (const float*)d_in[29]; const float* out_b= (const float*)d_in[30];
    float* out = (float*)d_out;

    const int smemBytes = SM_FLOATS * 4;
    cudaFuncSetAttribute(k_fused_mma, cudaFuncAttributeMaxDynamicSharedMemorySize, smemBytes);

    k_front<<<8751, 256>>>(node_repr, head_ids, tail_ids, rel_emb, she, ste,
                           A_w, A_b, C_w, C_b, E_w, E_b);
    k_fused_mma<<<Bg, 256, smemBytes>>>(node_repr, head_sis, tail_sis, t_label, hstp, tstp,
                                        B_w, B_b, Dm_w, Dm_b, G_w, G_b,
                                        head_ids, tail_ids, rel_lab, she, ste);
    k_ht<<<dim3(8, 8, 10), 256>>>(ht_w);
    k_final<<<Bg, 256>>>(node_repr, head_ids, tail_ids, rel_lab, rel_emb, ht_b,
                         fc_w, fc_b, out_w, out_b, out);
}